// round 16
// baseline (speedup 1.0000x reference)
#include <cuda_runtime.h>
#include <cuda_fp16.h>
#include <math.h>

// Problem constants
#define NB   16
#define HH   512
#define WW   512
#define HWp  (HH*WW)     // 262144
#define HW2  (HWp/2)     // 131072
#define NHWp (NB*HWp)    // 4194304
#define NHW2 (NB*HW2)    // 2097152
#define L2E  1.4426950408889634

typedef unsigned long long u64t;

// ---------------- packed f32x2 helpers ----------------
__device__ __forceinline__ u64t pk2(float lo, float hi){
  u64t r; asm("mov.b64 %0,{%1,%2};" : "=l"(r) : "f"(lo), "f"(hi)); return r;
}
__device__ __forceinline__ void upk2(u64t v, float& lo, float& hi){
  asm("mov.b64 {%0,%1},%2;" : "=f"(lo), "=f"(hi) : "l"(v));
}
__device__ __forceinline__ u64t fma2(u64t a, u64t b, u64t c){
  u64t d; asm("fma.rn.f32x2 %0,%1,%2,%3;" : "=l"(d) : "l"(a), "l"(b), "l"(c)); return d;
}

// ---------------- fast sigmoid (EX2 + RCP) ----------------
__device__ __forceinline__ float sigm(float x){
  float e, r;
  asm("ex2.approx.f32 %0, %1;" : "=f"(e) : "f"(-1.44269504f * x));
  asm("rcp.approx.f32 %0, %1;" : "=f"(r) : "f"(1.0f + e));
  return r;
}
// u already equals -log2e*(a*z+b)
__device__ __forceinline__ float sigm_pre(float u){
  float e, r;
  asm("ex2.approx.f32 %0, %1;" : "=f"(e) : "f"(u));
  asm("rcp.approx.f32 %0, %1;" : "=f"(r) : "f"(1.0f + e));
  return r;
}

// ---------------- constant weights ----------------
__constant__ float c_w1[160];
__constant__ float c_b1[16];
// packed {w,w} pairs: W1[0..159] B1[160..175] W2[176..431] B2[432..447]
//                     WC1[448..663] BC1[664..671] WC2[672..1823] BC2[1824..1839]
//                     W1K[1840..1959] B1K[1960..1964]
#define NDUP 1965
__constant__ u64t c_dup[NDUP];

// ---------------- device scratch ----------------
static __device__ __half2 g_th[33554432];  // z2 fp16: [16,16,512,512] as half2 (134 MB)
static __device__ float   g_x1[ 8388608];  // [16, 8,256,256]
static __device__ float   g_x2[ 4194304];  // [16,16,128,128]
static __device__ u64t    g_dup[NDUP];
static __device__ double  g_cov[75];
static __device__ double  g_sum2[16], g_sq2[16];
static __device__ double  g_vsum[NB*16], g_vsq[NB*16];
static __device__ double  g_usum[24], g_usq[24];

// ---------------- K_init: dup weights + zero accumulators ----------------
__global__ void k_init(const float* __restrict__ w1,  const float* __restrict__ b1,
                       const float* __restrict__ w2,  const float* __restrict__ b2,
                       const float* __restrict__ wc1, const float* __restrict__ bc1,
                       const float* __restrict__ wc2, const float* __restrict__ bc2,
                       const float* __restrict__ w1k, const float* __restrict__ b1k){
  int t = blockIdx.x*blockDim.x + threadIdx.x;
  if (t < 16){ g_sum2[t]=0.0; g_sq2[t]=0.0; }
  if (t < 24){ g_usum[t]=0.0; g_usq[t]=0.0; }
  if (t < 75){ g_cov[t]=0.0; }
  if (t < 256){ g_vsum[t]=0.0; g_vsq[t]=0.0; }
  float v; int ok = 1;
  if      (t < 160)  v = w1[t];
  else if (t < 176)  v = b1[t-160];
  else if (t < 432)  v = w2[t-176];
  else if (t < 448)  v = b2[t-432];
  else if (t < 664)  v = wc1[t-448];
  else if (t < 672)  v = bc1[t-664];
  else if (t < 1824) v = wc2[t-672];
  else if (t < 1840) v = bc2[t-1824];
  else if (t < 1960) v = w1k[t-1840];
  else if (t < 1965) v = b1k[t-1960];
  else ok = 0;
  if (ok) g_dup[t] = pk2(v, v);
}

// ---------------- K_cov: covariance stats of x ----------------
__global__ void __launch_bounds__(256,2) k_cov(const float* __restrict__ x){
  __shared__ double sred[75];
  int t = threadIdx.x;
  if (t < 75) sred[t] = 0.0;
  __syncthreads();

  float s[10], pp[55];
#pragma unroll
  for (int i=0;i<10;i++) s[i]=0.f;
#pragma unroll
  for (int k=0;k<55;k++) pp[k]=0.f;

  const float2* X = (const float2*)x;
  int stride = gridDim.x * blockDim.x;
  for (int p = blockIdx.x*blockDim.x + t; p < NHW2; p += stride){
    int n = p >> 17, pix = p & (HW2-1);
    const float2* xp = X + (size_t)n*10*HW2 + pix;
    float2 in[10];
#pragma unroll
    for (int i=0;i<10;i++) in[i] = xp[(size_t)i*HW2];
    int k = 0;
#pragma unroll
    for (int i=0;i<10;i++){
      s[i] += in[i].x + in[i].y;
#pragma unroll
      for (int j=i;j<10;j++){
        pp[k] = fmaf(in[i].x, in[j].x, fmaf(in[i].y, in[j].y, pp[k]));
        k++;
      }
    }
  }
#pragma unroll
  for (int i=0;i<10;i++){
    float a = s[i];
#pragma unroll
    for (int o=16;o>0;o>>=1) a += __shfl_down_sync(0xffffffffu,a,o);
    if ((t&31)==0) atomicAdd(&sred[i], (double)a);
  }
#pragma unroll
  for (int k=0;k<55;k++){
    float a = pp[k];
#pragma unroll
    for (int o=16;o>0;o>>=1) a += __shfl_down_sync(0xffffffffu,a,o);
    if ((t&31)==0) atomicAdd(&sred[10+k], (double)a);
  }
  __syncthreads();
  if (t < 75) atomicAdd(&g_cov[t], sred[t]);
}

// ---------------- K_fused: (BN1 coeffs) + conv1+BN1+sigm+conv2 -> z2(fp16), BN2 stats ----------------
// weights in SHARED (LDS floor 2 vs LDC floor 8)
__global__ void __launch_bounds__(256,2) k_fused(const float* __restrict__ x,
                                                 const float* __restrict__ gamma1,
                                                 const float* __restrict__ beta1){
  __shared__ u64t swd[448];            // W1|B1|W2|B2 packed pairs
  __shared__ float sa[16], sb[16];     // pre-folded: -log2e*a, -log2e*b
  __shared__ double ssum[16], ssq[16];
  int t = threadIdx.x;
  for (int i=t;i<448;i+=256) swd[i] = c_dup[i];
  if (t < 16){
    double m[10];
#pragma unroll
    for (int i=0;i<10;i++) m[i] = g_cov[i] / (double)NHWp;
    double mean = (double)c_b1[t];
#pragma unroll
    for (int i=0;i<10;i++) mean += (double)c_w1[t*10+i] * m[i];
    double var = 0.0;
    int k = 10;
#pragma unroll
    for (int i=0;i<10;i++){
#pragma unroll
      for (int j=i;j<10;j++){
        double cov = g_cov[k] / (double)NHWp - m[i]*m[j];
        double wp  = (double)c_w1[t*10+i] * (double)c_w1[t*10+j];
        var += (i==j ? 1.0 : 2.0) * wp * cov;
        k++;
      }
    }
    double a = (double)gamma1[t] / sqrt(var + 1e-5);
    double b = (double)beta1[t] - a*mean;
    sa[t] = (float)(-L2E * a);
    sb[t] = (float)(-L2E * b);
    ssum[t]=0.0; ssq[t]=0.0;
  }
  __syncthreads();

  float s[16], q[16];
#pragma unroll
  for (int c=0;c<16;c++){ s[c]=0.f; q[c]=0.f; }

  const u64t* X = (const u64t*)x;
  int stride = gridDim.x * blockDim.x;
  for (int p = blockIdx.x*blockDim.x + t; p < NHW2; p += stride){
    int n = p >> 17, pix = p & (HW2-1);
    const u64t* xp = X + (size_t)n*10*HW2 + pix;
    u64t in[10];
#pragma unroll
    for (int i=0;i<10;i++) in[i] = xp[(size_t)i*HW2];

    u64t acc[16];
#pragma unroll
    for (int o=0;o<16;o++) acc[o] = swd[432+o];

#pragma unroll
    for (int c=0;c<16;c++){
      u64t z = swd[160+c];
#pragma unroll
      for (int i=0;i<10;i++) z = fma2(swd[c*10+i], in[i], z);
      float zx, zy; upk2(z, zx, zy);
      float ac = sa[c], bc = sb[c];
      float yx = sigm_pre(fmaf(ac, zx, bc));
      float yy = sigm_pre(fmaf(ac, zy, bc));
      u64t y = pk2(yx, yy);
#pragma unroll
      for (int o=0;o<16;o++) acc[o] = fma2(swd[176+o*16+c], y, acc[o]);
    }
    __half2* op = g_th + (size_t)n*16*HW2 + pix;
#pragma unroll
    for (int o=0;o<16;o++){
      float ax, ay; upk2(acc[o], ax, ay);
      op[(size_t)o*HW2] = __float22half2_rn(make_float2(ax, ay));
      s[o] += ax + ay;
      q[o] = fmaf(ax, ax, fmaf(ay, ay, q[o]));
    }
  }
#pragma unroll
  for (int c=0;c<16;c++){
    float a=s[c], b=q[c];
#pragma unroll
    for (int o=16;o>0;o>>=1){ a += __shfl_down_sync(0xffffffffu,a,o); b += __shfl_down_sync(0xffffffffu,b,o); }
    if ((t&31)==0){ atomicAdd(&ssum[c],(double)a); atomicAdd(&ssq[c],(double)b); }
  }
  __syncthreads();
  if (t<16){ atomicAdd(&g_sum2[t], ssum[t]); atomicAdd(&g_sq2[t], ssq[t]); }
}

// ---------------- K_varstats: 8 blocks per (n,c), uint4 loads, atomic finish ----------------
__global__ void __launch_bounds__(256) k_varstats(const float* __restrict__ gamma2,
                                                  const float* __restrict__ beta2){
  int bid = blockIdx.x;           // 0..2047
  int nc  = bid >> 3;             // (n,c)
  int seg = bid & 7;
  int c   = nc & 15;
  int t = threadIdx.x;

  double m = g_sum2[c] / (double)NHWp;
  double v = g_sq2[c]  / (double)NHWp - m*m;
  double a = (double)gamma2[c] / sqrt(v + 1e-5);
  double b = (double)beta2[c] - a*m;
  float ap = (float)(-L2E * a);
  float bp = (float)(-L2E * b);

  // channel = 262144 halves = 32768 uint4; segment = 4096 uint4
  const uint4* base = (const uint4*)g_th + (size_t)nc*32768 + seg*4096;
  float s0=0.f,s1=0.f,s2=0.f,s3=0.f, q0=0.f,q1=0.f,q2=0.f,q3=0.f;
#pragma unroll 4
  for (int i = t; i < 4096; i += 256){
    uint4 d = base[i];
    float2 f0 = __half22float2(*(__half2*)&d.x);
    float2 f1 = __half22float2(*(__half2*)&d.y);
    float2 f2 = __half22float2(*(__half2*)&d.z);
    float2 f3 = __half22float2(*(__half2*)&d.w);
    float h0 = sigm_pre(fmaf(ap, f0.x, bp));
    float h1 = sigm_pre(fmaf(ap, f0.y, bp));
    float h2 = sigm_pre(fmaf(ap, f1.x, bp));
    float h3 = sigm_pre(fmaf(ap, f1.y, bp));
    float h4 = sigm_pre(fmaf(ap, f2.x, bp));
    float h5 = sigm_pre(fmaf(ap, f2.y, bp));
    float h6 = sigm_pre(fmaf(ap, f3.x, bp));
    float h7 = sigm_pre(fmaf(ap, f3.y, bp));
    s0 += h0+h4; q0 = fmaf(h0,h0, fmaf(h4,h4, q0));
    s1 += h1+h5; q1 = fmaf(h1,h1, fmaf(h5,h5, q1));
    s2 += h2+h6; q2 = fmaf(h2,h2, fmaf(h6,h6, q2));
    s3 += h3+h7; q3 = fmaf(h3,h3, fmaf(h7,h7, q3));
  }
  float s = (s0+s1)+(s2+s3);
  float q = (q0+q1)+(q2+q3);
#pragma unroll
  for (int o=16;o>0;o>>=1){ s += __shfl_down_sync(0xffffffffu,s,o); q += __shfl_down_sync(0xffffffffu,q,o); }

  __shared__ double sh_s[8], sh_q[8];
  if ((t&31)==0){ sh_s[t>>5] = (double)s; sh_q[t>>5] = (double)q; }
  __syncthreads();
  if (t==0){
    double S=0.0, Q=0.0;
#pragma unroll
    for (int w=0;w<8;w++){ S += sh_s[w]; Q += sh_q[w]; }
    atomicAdd(&g_vsum[nc], S);
    atomicAdd(&g_vsq [nc], Q);
  }
}

// ---------------- K_conv3a: (BN2 + top-3) + conv3x3(3->8)+sigm+pool; shared weights ----------------
__global__ void __launch_bounds__(256,2) k_conv3a(const float* __restrict__ gamma2,
                                                  const float* __restrict__ beta2){
  __shared__ float sp[3][34][36];
  __shared__ u64t  swc[224];            // WC1(216)+BC1(8), contiguous at c_dup[448..671]
  __shared__ float sa16[16], sb16[16];
  __shared__ double svar[16];
  __shared__ int   sidx[3];
  __shared__ float sa[3], sbb[3];
  __shared__ int   sch[3];
  int n = blockIdx.z;
  int t = threadIdx.x;
  if (t < 224) swc[t] = c_dup[448+t];
  if (t < 16){
    double m = g_sum2[t] / (double)NHWp;
    double v = g_sq2[t]  / (double)NHWp - m*m;
    double a = (double)gamma2[t] / sqrt(v + 1e-5);
    double b = (double)beta2[t] - a*m;
    sa16[t] = (float)(-L2E * a);
    sb16[t] = (float)(-L2E * b);
    double su = g_vsum[n*16+t], qq = g_vsq[n*16+t];
    double mm = su / (double)HWp;
    svar[t] = (qq - su*mm) / (double)(HWp - 1);
  }
  __syncthreads();
  if (t == 0){
    int mask = 0;
    for (int k=0;k<3;k++){
      int best = 0; double bv = -1e300;
      for (int c=0;c<16;c++)
        if (!((mask>>c)&1) && svar[c] > bv){ bv = svar[c]; best = c; }
      mask |= 1<<best;
      sidx[k] = best;
    }
  }
  __syncthreads();
  if (t < 3){ int ch = sidx[t]; sch[t]=ch; sa[t]=sa16[ch]; sbb[t]=sb16[ch]; }
  __syncthreads();

  const __half* H = (const __half*)g_th;
  int gy0 = blockIdx.y*32 - 1, gx0 = blockIdx.x*32 - 1;
  for (int i=t; i < 3*34*34; i += 256){
    int c = i / 1156, rem = i % 1156;
    int r = rem / 34, col = rem % 34;
    int gy = gy0 + r, gx = gx0 + col;
    float v = 0.f;
    if (gy >= 0 && gy < HH && gx >= 0 && gx < WW)
      v = sigm_pre(fmaf(sa[c], __half2float(H[(size_t)(n*16+sch[c])*HWp + gy*WW + gx]), sbb[c]));
    sp[c][r][col] = v;
  }
  __syncthreads();

  int tx = t & 15, ty = t >> 4;
  int by = 2*ty, bx = 2*tx;
  u64t aA[8], aB[8];
#pragma unroll
  for (int oc=0;oc<8;oc++){ aA[oc]=swc[216+oc]; aB[oc]=swc[216+oc]; }
#pragma unroll
  for (int c=0;c<3;c++)
#pragma unroll
    for (int ky=0;ky<3;ky++)
#pragma unroll
      for (int kx=0;kx<3;kx++){
        u64t vA = pk2(sp[c][by+ky  ][bx+kx], sp[c][by+ky  ][bx+kx+1]);
        u64t vB = pk2(sp[c][by+ky+1][bx+kx], sp[c][by+ky+1][bx+kx+1]);
#pragma unroll
        for (int oc=0;oc<8;oc++){
          u64t wv = swc[oc*27 + c*9 + ky*3 + kx];
          aA[oc] = fma2(wv, vA, aA[oc]);
          aB[oc] = fma2(wv, vB, aB[oc]);
        }
      }
  int py = blockIdx.y*16 + ty, px = blockIdx.x*16 + tx;
#pragma unroll
  for (int oc=0;oc<8;oc++){
    float a00,a01,a10,a11;
    upk2(aA[oc],a00,a01); upk2(aB[oc],a10,a11);
    float mx = fmaxf(fmaxf(a00,a01), fmaxf(a10,a11));
    g_x1[(size_t)(n*8+oc)*65536 + py*256 + px] = sigm(mx);  // sigmoid monotone
  }
}

// ---------------- K_conv3b: conv3x3(8->16)+sigm+pool; shared weights ----------------
__global__ void __launch_bounds__(256,2) k_conv3b(){
  __shared__ float sp[8][34][36];       // 39168 B
  __shared__ u64t  swc[1168];           // WC2(1152)+BC2(16) at c_dup[672..1839]; 9344 B
  int n = blockIdx.z;
  int t = threadIdx.x;
  for (int i=t;i<1168;i+=256) swc[i] = c_dup[672+i];

  int gy0 = blockIdx.y*32 - 1, gx0 = blockIdx.x*32 - 1;
  for (int i=t; i < 8*34*34; i += 256){
    int c = i / 1156, rem = i % 1156;
    int r = rem / 34, col = rem % 34;
    int gy = gy0 + r, gx = gx0 + col;
    float v = 0.f;
    if (gy >= 0 && gy < 256 && gx >= 0 && gx < 256)
      v = g_x1[(size_t)(n*8+c)*65536 + gy*256 + gx];
    sp[c][r][col] = v;
  }
  __syncthreads();

  int tx = t & 15, ty = t >> 4;
  int by = 2*ty, bx = 2*tx;
  u64t aA[16], aB[16];
#pragma unroll
  for (int oc=0;oc<16;oc++){ aA[oc]=swc[1152+oc]; aB[oc]=swc[1152+oc]; }
#pragma unroll
  for (int c=0;c<8;c++)
#pragma unroll
    for (int ky=0;ky<3;ky++)
#pragma unroll
      for (int kx=0;kx<3;kx++){
        u64t vA = pk2(sp[c][by+ky  ][bx+kx], sp[c][by+ky  ][bx+kx+1]);
        u64t vB = pk2(sp[c][by+ky+1][bx+kx], sp[c][by+ky+1][bx+kx+1]);
#pragma unroll
        for (int oc=0;oc<16;oc++){
          u64t wv = swc[oc*72 + c*9 + ky*3 + kx];
          aA[oc] = fma2(wv, vA, aA[oc]);
          aB[oc] = fma2(wv, vB, aB[oc]);
        }
      }
  int py = blockIdx.y*16 + ty, px = blockIdx.x*16 + tx;
#pragma unroll
  for (int oc=0;oc<16;oc++){
    float a00,a01,a10,a11;
    upk2(aA[oc],a00,a01); upk2(aB[oc],a10,a11);
    float mx = fmaxf(fmaxf(a00,a01), fmaxf(a10,a11));
    g_x2[(size_t)(n*16+oc)*16384 + py*128 + px] = sigm(mx);
  }
}

// ---- vertical index helpers (jax half-pixel bilinear, clamped) ----
__device__ __forceinline__ void idx_up2(int h, int Hin, int& y0, int& y1, float& f){
  y0 = (h >> 1) - ((h & 1) ^ 1);
  f  = (h & 1) ? 0.25f : 0.75f;
  y1 = min(y0 + 1, Hin - 1);
  y0 = max(y0, 0);
}
__device__ __forceinline__ void idx_up4(int h, int Hin, int& y0, int& y1, float& f){
  int m = h & 3;
  y0 = (h >> 2) - (m < 2 ? 1 : 0);
  f  = (m==0) ? 0.625f : (m==1) ? 0.875f : (m==2) ? 0.125f : 0.375f;
  y1 = min(y0 + 1, Hin - 1);
  y0 = max(y0, 0);
}
#define LERP(a,b,f) ((a) + (f)*((b)-(a)))

// sigmoid outputs > 0 and bilinear weights nonneg => relu identity on up paths.

// ---------------- K_upstats: stats of up2(x1) and up4(x2), merged ----------------
__global__ void __launch_bounds__(256,2) k_upstats(){
  __shared__ double ssum[24], ssq[24];
  int t = threadIdx.x;
  if (t < 24){ ssum[t]=0.0; ssq[t]=0.0; }
  __syncthreads();

  float s[24], q[24];
#pragma unroll
  for (int c=0;c<24;c++){ s[c]=0.f; q[c]=0.f; }

  const int NQ = NHWp/4;
  int stride = gridDim.x * blockDim.x;
  for (int p = blockIdx.x*blockDim.x + t; p < NQ; p += stride){
    int n = p >> 16, r = p & 65535;
    int h = r >> 7, w = r & 127;
    {   // up2 path
      int y0,y1; float fy; idx_up2(h,256,y0,y1,fy);
      int c0 = max(2*w-1,0), c1 = 2*w, c2 = 2*w+1, c3 = min(2*w+2,255);
      const float* bp = g_x1 + (size_t)n*8*65536;
#pragma unroll
      for (int c=0;c<8;c++){
        const float* p0 = bp + (size_t)c*65536 + y0*256;
        const float* p1 = bp + (size_t)c*65536 + y1*256;
        float vv0 = LERP(p0[c0], p1[c0], fy);
        float vv1 = LERP(p0[c1], p1[c1], fy);
        float vv2 = LERP(p0[c2], p1[c2], fy);
        float vv3 = LERP(p0[c3], p1[c3], fy);
        float o0 = LERP(vv0, vv1, 0.75f);
        float o1 = LERP(vv1, vv2, 0.25f);
        float o2 = LERP(vv1, vv2, 0.75f);
        float o3 = LERP(vv2, vv3, 0.25f);
        s[c] += (o0+o1) + (o2+o3);
        q[c] = fmaf(o0,o0, fmaf(o1,o1, fmaf(o2,o2, fmaf(o3,o3, q[c]))));
      }
    }
    {   // up4 path
      int y0,y1; float fy; idx_up4(h,128,y0,y1,fy);
      int cm = max(w-1,0), cc = w, cp = min(w+1,127);
      const float* bp = g_x2 + (size_t)n*16*16384;
#pragma unroll
      for (int c=0;c<16;c++){
        const float* p0 = bp + (size_t)c*16384 + y0*128;
        const float* p1 = bp + (size_t)c*16384 + y1*128;
        float vv0 = LERP(p0[cm], p1[cm], fy);
        float vv1 = LERP(p0[cc], p1[cc], fy);
        float vv2 = LERP(p0[cp], p1[cp], fy);
        float o0 = LERP(vv0, vv1, 0.625f);
        float o1 = LERP(vv0, vv1, 0.875f);
        float o2 = LERP(vv1, vv2, 0.125f);
        float o3 = LERP(vv1, vv2, 0.375f);
        s[8+c] += (o0+o1) + (o2+o3);
        q[8+c] = fmaf(o0,o0, fmaf(o1,o1, fmaf(o2,o2, fmaf(o3,o3, q[8+c]))));
      }
    }
  }
#pragma unroll
  for (int c=0;c<24;c++){
    float a=s[c], b=q[c];
#pragma unroll
    for (int o=16;o>0;o>>=1){ a += __shfl_down_sync(0xffffffffu,a,o); b += __shfl_down_sync(0xffffffffu,b,o); }
    if ((t&31)==0){ atomicAdd(&ssum[c],(double)a); atomicAdd(&ssq[c],(double)b); }
  }
  __syncthreads();
  if (t<24){ atomicAdd(&g_usum[t], ssum[t]); atomicAdd(&g_usq[t], ssq[t]); }
}

// ---------------- K_final: (up BN coeffs) + up2/up4 + BN + concat + 1x1 conv; shared weights ----------------
__global__ void __launch_bounds__(256,3) k_final(float* __restrict__ out,
                                                 const float* __restrict__ gbn1,
                                                 const float* __restrict__ bbn1,
                                                 const float* __restrict__ gbn2,
                                                 const float* __restrict__ bbn2){
  __shared__ u64t swf[125];            // W1K(120)+B1K(5) at c_dup[1840..1964]
  __shared__ float sa[24], sbb[24];
  int t = threadIdx.x;
  if (t < 125) swf[t] = c_dup[1840+t];
  if (t < 24){
    double m = g_usum[t] / (double)NHWp;
    double v = g_usq[t]  / (double)NHWp - m*m;
    double gamma = (t < 8) ? (double)gbn2[t] : (double)gbn1[t-8];
    double beta  = (t < 8) ? (double)bbn2[t] : (double)bbn1[t-8];
    double a = gamma / sqrt(v + 1e-5);
    sa[t]  = (float)a;
    sbb[t] = (float)(beta - a*m);
  }
  __syncthreads();

  const int NQ = NHWp/4;
  int stride = gridDim.x * blockDim.x;
  for (int p = blockIdx.x*blockDim.x + t; p < NQ; p += stride){
    int n = p >> 16, r = p & 65535;
    int h = r >> 7, w = r & 127;

    u64t a01[5], a23[5];
#pragma unroll
    for (int k=0;k<5;k++){ a01[k]=swf[120+k]; a23[k]=swf[120+k]; }

    {   // up2 path: channels 0..7
      int y0,y1; float fy; idx_up2(h,256,y0,y1,fy);
      int c0 = max(2*w-1,0), c1 = 2*w, c2 = 2*w+1, c3 = min(2*w+2,255);
      const float* bp = g_x1 + (size_t)n*8*65536;
#pragma unroll
      for (int c=0;c<8;c++){
        const float* p0 = bp + (size_t)c*65536 + y0*256;
        const float* p1 = bp + (size_t)c*65536 + y1*256;
        float vv0 = LERP(p0[c0], p1[c0], fy);
        float vv1 = LERP(p0[c1], p1[c1], fy);
        float vv2 = LERP(p0[c2], p1[c2], fy);
        float vv3 = LERP(p0[c3], p1[c3], fy);
        float sc = sa[c], sh = sbb[c];
        float r0 = fmaf(sc, LERP(vv0, vv1, 0.75f), sh);
        float r1 = fmaf(sc, LERP(vv1, vv2, 0.25f), sh);
        float r2 = fmaf(sc, LERP(vv1, vv2, 0.75f), sh);
        float r3 = fmaf(sc, LERP(vv2, vv3, 0.25f), sh);
        u64t r01 = pk2(r0,r1), r23 = pk2(r2,r3);
#pragma unroll
        for (int k=0;k<5;k++){
          u64t wv = swf[k*24+c];
          a01[k] = fma2(wv, r01, a01[k]);
          a23[k] = fma2(wv, r23, a23[k]);
        }
      }
    }
    {   // up4 path: channels 8..23
      int y0,y1; float fy; idx_up4(h,128,y0,y1,fy);
      int cm = max(w-1,0), cc = w, cp = min(w+1,127);
      const float* bp = g_x2 + (size_t)n*16*16384;
#pragma unroll
      for (int c=0;c<16;c++){
        const float* p0 = bp + (size_t)c*16384 + y0*128;
        const float* p1 = bp + (size_t)c*16384 + y1*128;
        float vv0 = LERP(p0[cm], p1[cm], fy);
        float vv1 = LERP(p0[cc], p1[cc], fy);
        float vv2 = LERP(p0[cp], p1[cp], fy);
        float sc = sa[8+c], sh = sbb[8+c];
        float r0 = fmaf(sc, LERP(vv0, vv1, 0.625f), sh);
        float r1 = fmaf(sc, LERP(vv0, vv1, 0.875f), sh);
        float r2 = fmaf(sc, LERP(vv1, vv2, 0.125f), sh);
        float r3 = fmaf(sc, LERP(vv1, vv2, 0.375f), sh);
        u64t r01 = pk2(r0,r1), r23 = pk2(r2,r3);
#pragma unroll
        for (int k=0;k<5;k++){
          u64t wv = swf[k*24+8+c];
          a01[k] = fma2(wv, r01, a01[k]);
          a23[k] = fma2(wv, r23, a23[k]);
        }
      }
    }
#pragma unroll
    for (int k=0;k<5;k++){
      float4 v;
      upk2(a01[k], v.x, v.y);
      upk2(a23[k], v.z, v.w);
      *(float4*)(out + (size_t)(n*5+k)*HWp + h*512 + 4*w) = v;
    }
  }
}

// ---------------- launch ----------------
extern "C" void kernel_launch(void* const* d_in, const int* in_sizes, int n_in,
                              void* d_out, int out_size){
  (void)in_sizes; (void)n_in; (void)out_size;
  const float* x       = (const float*)d_in[0];
  const float* g_ebn1  = (const float*)d_in[3];
  const float* be_ebn1 = (const float*)d_in[4];
  const float* g_ebn2  = (const float*)d_in[7];
  const float* be_ebn2 = (const float*)d_in[8];
  const float* g_bn1   = (const float*)d_in[13];
  const float* be_bn1  = (const float*)d_in[14];
  const float* g_bn2   = (const float*)d_in[15];
  const float* be_bn2  = (const float*)d_in[16];
  float* out = (float*)d_out;

  cudaMemcpyToSymbolAsync(c_w1, d_in[1], 160*sizeof(float), 0, cudaMemcpyDeviceToDevice, 0);
  cudaMemcpyToSymbolAsync(c_b1, d_in[2],  16*sizeof(float), 0, cudaMemcpyDeviceToDevice, 0);

  k_init<<<8,256>>>((const float*)d_in[1],  (const float*)d_in[2],
                    (const float*)d_in[5],  (const float*)d_in[6],
                    (const float*)d_in[9],  (const float*)d_in[10],
                    (const float*)d_in[11], (const float*)d_in[12],
                    (const float*)d_in[17], (const float*)d_in[18]);
  void* pdup = nullptr;
  cudaGetSymbolAddress(&pdup, g_dup);
  cudaMemcpyToSymbolAsync(c_dup, pdup, NDUP*sizeof(u64t), 0, cudaMemcpyDeviceToDevice, 0);

  const int GS2 = 1184;   // occ-2 kernels: 148*8
  const int GS3 = 1332;   // occ-3 kernels: 148*9

  k_cov<<<GS2,256>>>(x);
  k_fused<<<GS2,256>>>(x, g_ebn1, be_ebn1);
  k_varstats<<<2048,256>>>(g_ebn2, be_ebn2);
  k_conv3a<<<dim3(16,16,16),256>>>(g_ebn2, be_ebn2);
  k_conv3b<<<dim3(8,8,16),256>>>();
  k_upstats<<<GS2,256>>>();
  k_final<<<GS3,256>>>(out, g_bn1, be_bn1, g_bn2, be_bn2);
}

// round 17
// speedup vs baseline: 3.2190x; 3.2190x over previous
#include <cuda_runtime.h>
#include <cuda_fp16.h>
#include <math.h>

// Problem constants
#define NB   16
#define HH   512
#define WW   512
#define HWp  (HH*WW)     // 262144
#define HW2  (HWp/2)     // 131072
#define NHWp (NB*HWp)    // 4194304
#define NHW2 (NB*HW2)    // 2097152
#define L2E  1.4426950408889634

typedef unsigned long long u64t;

// ---------------- packed f32x2 helpers ----------------
__device__ __forceinline__ u64t pk2(float lo, float hi){
  u64t r; asm("mov.b64 %0,{%1,%2};" : "=l"(r) : "f"(lo), "f"(hi)); return r;
}
__device__ __forceinline__ void upk2(u64t v, float& lo, float& hi){
  asm("mov.b64 {%0,%1},%2;" : "=f"(lo), "=f"(hi) : "l"(v));
}
__device__ __forceinline__ u64t fma2(u64t a, u64t b, u64t c){
  u64t d; asm("fma.rn.f32x2 %0,%1,%2,%3;" : "=l"(d) : "l"(a), "l"(b), "l"(c)); return d;
}

// ---------------- fast sigmoid (EX2 + RCP) ----------------
__device__ __forceinline__ float sigm(float x){
  float e, r;
  asm("ex2.approx.f32 %0, %1;" : "=f"(e) : "f"(-1.44269504f * x));
  asm("rcp.approx.f32 %0, %1;" : "=f"(r) : "f"(1.0f + e));
  return r;
}
// u already equals -log2e*(a*z+b)
__device__ __forceinline__ float sigm_pre(float u){
  float e, r;
  asm("ex2.approx.f32 %0, %1;" : "=f"(e) : "f"(u));
  asm("rcp.approx.f32 %0, %1;" : "=f"(r) : "f"(1.0f + e));
  return r;
}

// ---------------- constant weights (constant port overlaps LSU — keep here!) ----------------
__constant__ float c_w1[160];
__constant__ float c_b1[16];
#define NDUP 1965
__constant__ u64t c_dup[NDUP];
#define DW1(i)  c_dup[(i)]
#define DB1(i)  c_dup[160+(i)]
#define DW2(i)  c_dup[176+(i)]
#define DB2(i)  c_dup[432+(i)]
#define DWC1(i) c_dup[448+(i)]
#define DBC1(i) c_dup[664+(i)]
#define DWC2(i) c_dup[672+(i)]
#define DBC2(i) c_dup[1824+(i)]
#define DW1K(i) c_dup[1840+(i)]
#define DB1K(i) c_dup[1960+(i)]

// ---------------- device scratch ----------------
static __device__ __half2 g_th[33554432];  // z2 fp16: [16,16,512,512] as half2 (134 MB)
static __device__ float   g_x1[ 8388608];  // [16, 8,256,256]
static __device__ float   g_x2[ 4194304];  // [16,16,128,128]
static __device__ u64t    g_dup[NDUP];
static __device__ double  g_cov[75];
static __device__ double  g_sum2[16], g_sq2[16];
static __device__ double  g_vsum[NB*16], g_vsq[NB*16];
static __device__ double  g_usum[24], g_usq[24];

// ---------------- K_init: dup weights + zero accumulators ----------------
__global__ void k_init(const float* __restrict__ w1,  const float* __restrict__ b1,
                       const float* __restrict__ w2,  const float* __restrict__ b2,
                       const float* __restrict__ wc1, const float* __restrict__ bc1,
                       const float* __restrict__ wc2, const float* __restrict__ bc2,
                       const float* __restrict__ w1k, const float* __restrict__ b1k){
  int t = blockIdx.x*blockDim.x + threadIdx.x;
  if (t < 16){ g_sum2[t]=0.0; g_sq2[t]=0.0; }
  if (t < 24){ g_usum[t]=0.0; g_usq[t]=0.0; }
  if (t < 75){ g_cov[t]=0.0; }
  if (t < 256){ g_vsum[t]=0.0; g_vsq[t]=0.0; }
  float v; int ok = 1;
  if      (t < 160)  v = w1[t];
  else if (t < 176)  v = b1[t-160];
  else if (t < 432)  v = w2[t-176];
  else if (t < 448)  v = b2[t-432];
  else if (t < 664)  v = wc1[t-448];
  else if (t < 672)  v = bc1[t-664];
  else if (t < 1824) v = wc2[t-672];
  else if (t < 1840) v = bc2[t-1824];
  else if (t < 1960) v = w1k[t-1840];
  else if (t < 1965) v = b1k[t-1960];
  else ok = 0;
  if (ok) g_dup[t] = pk2(v, v);
}

// ---------------- K_cov: covariance stats of x ----------------
__global__ void __launch_bounds__(256,2) k_cov(const float* __restrict__ x){
  __shared__ double sred[75];
  int t = threadIdx.x;
  if (t < 75) sred[t] = 0.0;
  __syncthreads();

  float s[10], pp[55];
#pragma unroll
  for (int i=0;i<10;i++) s[i]=0.f;
#pragma unroll
  for (int k=0;k<55;k++) pp[k]=0.f;

  const float2* X = (const float2*)x;
  int stride = gridDim.x * blockDim.x;
  for (int p = blockIdx.x*blockDim.x + t; p < NHW2; p += stride){
    int n = p >> 17, pix = p & (HW2-1);
    const float2* xp = X + (size_t)n*10*HW2 + pix;
    float2 in[10];
#pragma unroll
    for (int i=0;i<10;i++) in[i] = xp[(size_t)i*HW2];
    int k = 0;
#pragma unroll
    for (int i=0;i<10;i++){
      s[i] += in[i].x + in[i].y;
#pragma unroll
      for (int j=i;j<10;j++){
        pp[k] = fmaf(in[i].x, in[j].x, fmaf(in[i].y, in[j].y, pp[k]));
        k++;
      }
    }
  }
#pragma unroll
  for (int i=0;i<10;i++){
    float a = s[i];
#pragma unroll
    for (int o=16;o>0;o>>=1) a += __shfl_down_sync(0xffffffffu,a,o);
    if ((t&31)==0) atomicAdd(&sred[i], (double)a);
  }
#pragma unroll
  for (int k=0;k<55;k++){
    float a = pp[k];
#pragma unroll
    for (int o=16;o>0;o>>=1) a += __shfl_down_sync(0xffffffffu,a,o);
    if ((t&31)==0) atomicAdd(&sred[10+k], (double)a);
  }
  __syncthreads();
  if (t < 75) atomicAdd(&g_cov[t], sred[t]);
}

// ---------------- K_fused: (BN1 coeffs) + conv1+BN1+sigm+conv2 -> z2(fp16), BN2 stats ----------------
__global__ void __launch_bounds__(256,2) k_fused(const float* __restrict__ x,
                                                 const float* __restrict__ gamma1,
                                                 const float* __restrict__ beta1){
  __shared__ float sa[16], sb[16];     // pre-folded: -log2e*a, -log2e*b
  __shared__ double ssum[16], ssq[16];
  int t = threadIdx.x;
  if (t < 16){
    double m[10];
#pragma unroll
    for (int i=0;i<10;i++) m[i] = g_cov[i] / (double)NHWp;
    double mean = (double)c_b1[t];
#pragma unroll
    for (int i=0;i<10;i++) mean += (double)c_w1[t*10+i] * m[i];
    double var = 0.0;
    int k = 10;
#pragma unroll
    for (int i=0;i<10;i++){
#pragma unroll
      for (int j=i;j<10;j++){
        double cov = g_cov[k] / (double)NHWp - m[i]*m[j];
        double wp  = (double)c_w1[t*10+i] * (double)c_w1[t*10+j];
        var += (i==j ? 1.0 : 2.0) * wp * cov;
        k++;
      }
    }
    double a = (double)gamma1[t] / sqrt(var + 1e-5);
    double b = (double)beta1[t] - a*mean;
    sa[t] = (float)(-L2E * a);
    sb[t] = (float)(-L2E * b);
    ssum[t]=0.0; ssq[t]=0.0;
  }
  __syncthreads();

  float s[16], q[16];
#pragma unroll
  for (int c=0;c<16;c++){ s[c]=0.f; q[c]=0.f; }

  const u64t* X = (const u64t*)x;
  int stride = gridDim.x * blockDim.x;
  for (int p = blockIdx.x*blockDim.x + t; p < NHW2; p += stride){
    int n = p >> 17, pix = p & (HW2-1);
    const u64t* xp = X + (size_t)n*10*HW2 + pix;
    u64t in[10];
#pragma unroll
    for (int i=0;i<10;i++) in[i] = xp[(size_t)i*HW2];

    u64t acc[16];
#pragma unroll
    for (int o=0;o<16;o++) acc[o] = DB2(o);

#pragma unroll
    for (int c=0;c<16;c++){
      u64t z = DB1(c);
#pragma unroll
      for (int i=0;i<10;i++) z = fma2(DW1(c*10+i), in[i], z);
      float zx, zy; upk2(z, zx, zy);
      float ac = sa[c], bc = sb[c];
      float yx = sigm_pre(fmaf(ac, zx, bc));
      float yy = sigm_pre(fmaf(ac, zy, bc));
      u64t y = pk2(yx, yy);
#pragma unroll
      for (int o=0;o<16;o++) acc[o] = fma2(DW2(o*16+c), y, acc[o]);
    }
    __half2* op = g_th + (size_t)n*16*HW2 + pix;
#pragma unroll
    for (int o=0;o<16;o++){
      float ax, ay; upk2(acc[o], ax, ay);
      op[(size_t)o*HW2] = __float22half2_rn(make_float2(ax, ay));
      s[o] += ax + ay;
      q[o] = fmaf(ax, ax, fmaf(ay, ay, q[o]));
    }
  }
#pragma unroll
  for (int c=0;c<16;c++){
    float a=s[c], b=q[c];
#pragma unroll
    for (int o=16;o>0;o>>=1){ a += __shfl_down_sync(0xffffffffu,a,o); b += __shfl_down_sync(0xffffffffu,b,o); }
    if ((t&31)==0){ atomicAdd(&ssum[c],(double)a); atomicAdd(&ssq[c],(double)b); }
  }
  __syncthreads();
  if (t<16){ atomicAdd(&g_sum2[t], ssum[t]); atomicAdd(&g_sq2[t], ssq[t]); }
}

// ---------------- K_varstats: 8 blocks per (n,c), uint4 loads, atomic finish (verified 48us) ----------------
__global__ void __launch_bounds__(256) k_varstats(const float* __restrict__ gamma2,
                                                  const float* __restrict__ beta2){
  int bid = blockIdx.x;           // 0..2047
  int nc  = bid >> 3;             // (n,c)
  int seg = bid & 7;
  int c   = nc & 15;
  int t = threadIdx.x;

  double m = g_sum2[c] / (double)NHWp;
  double v = g_sq2[c]  / (double)NHWp - m*m;
  double a = (double)gamma2[c] / sqrt(v + 1e-5);
  double b = (double)beta2[c] - a*m;
  float ap = (float)(-L2E * a);
  float bp = (float)(-L2E * b);

  // channel = 262144 halves = 32768 uint4; segment = 4096 uint4
  const uint4* base = (const uint4*)g_th + (size_t)nc*32768 + seg*4096;
  float s0=0.f,s1=0.f,s2=0.f,s3=0.f, q0=0.f,q1=0.f,q2=0.f,q3=0.f;
#pragma unroll 4
  for (int i = t; i < 4096; i += 256){
    uint4 d = base[i];
    float2 f0 = __half22float2(*(__half2*)&d.x);
    float2 f1 = __half22float2(*(__half2*)&d.y);
    float2 f2 = __half22float2(*(__half2*)&d.z);
    float2 f3 = __half22float2(*(__half2*)&d.w);
    float h0 = sigm_pre(fmaf(ap, f0.x, bp));
    float h1 = sigm_pre(fmaf(ap, f0.y, bp));
    float h2 = sigm_pre(fmaf(ap, f1.x, bp));
    float h3 = sigm_pre(fmaf(ap, f1.y, bp));
    float h4 = sigm_pre(fmaf(ap, f2.x, bp));
    float h5 = sigm_pre(fmaf(ap, f2.y, bp));
    float h6 = sigm_pre(fmaf(ap, f3.x, bp));
    float h7 = sigm_pre(fmaf(ap, f3.y, bp));
    s0 += h0+h4; q0 = fmaf(h0,h0, fmaf(h4,h4, q0));
    s1 += h1+h5; q1 = fmaf(h1,h1, fmaf(h5,h5, q1));
    s2 += h2+h6; q2 = fmaf(h2,h2, fmaf(h6,h6, q2));
    s3 += h3+h7; q3 = fmaf(h3,h3, fmaf(h7,h7, q3));
  }
  float s = (s0+s1)+(s2+s3);
  float q = (q0+q1)+(q2+q3);
#pragma unroll
  for (int o=16;o>0;o>>=1){ s += __shfl_down_sync(0xffffffffu,s,o); q += __shfl_down_sync(0xffffffffu,q,o); }

  __shared__ double sh_s[8], sh_q[8];
  if ((t&31)==0){ sh_s[t>>5] = (double)s; sh_q[t>>5] = (double)q; }
  __syncthreads();
  if (t==0){
    double S=0.0, Q=0.0;
#pragma unroll
    for (int w=0;w<8;w++){ S += sh_s[w]; Q += sh_q[w]; }
    atomicAdd(&g_vsum[nc], S);
    atomicAdd(&g_vsq [nc], Q);
  }
}

// ---------------- K_conv3a: (BN2 coeffs + top-3) + conv3x3(3->8)+sigm+pool ----------------
__global__ void __launch_bounds__(256,2) k_conv3a(const float* __restrict__ gamma2,
                                                  const float* __restrict__ beta2){
  __shared__ float sp[3][34][36];
  __shared__ float sa16[16], sb16[16];   // folded -log2e coeffs
  __shared__ double svar[16];
  __shared__ int   sidx[3];
  __shared__ float sa[3], sbb[3];
  __shared__ int   sch[3];
  int n = blockIdx.z;
  int t = threadIdx.x;
  if (t < 16){
    double m = g_sum2[t] / (double)NHWp;
    double v = g_sq2[t]  / (double)NHWp - m*m;
    double a = (double)gamma2[t] / sqrt(v + 1e-5);
    double b = (double)beta2[t] - a*m;
    sa16[t] = (float)(-L2E * a);
    sb16[t] = (float)(-L2E * b);
    double su = g_vsum[n*16+t], qq = g_vsq[n*16+t];
    double mm = su / (double)HWp;
    svar[t] = (qq - su*mm) / (double)(HWp - 1);
  }
  __syncthreads();
  if (t == 0){
    int mask = 0;
    for (int k=0;k<3;k++){
      int best = 0; double bv = -1e300;
      for (int c=0;c<16;c++)
        if (!((mask>>c)&1) && svar[c] > bv){ bv = svar[c]; best = c; }
      mask |= 1<<best;
      sidx[k] = best;
    }
  }
  __syncthreads();
  if (t < 3){ int ch = sidx[t]; sch[t]=ch; sa[t]=sa16[ch]; sbb[t]=sb16[ch]; }
  __syncthreads();

  const __half* H = (const __half*)g_th;
  int gy0 = blockIdx.y*32 - 1, gx0 = blockIdx.x*32 - 1;
  for (int i=t; i < 3*34*34; i += 256){
    int c = i / 1156, rem = i % 1156;
    int r = rem / 34, col = rem % 34;
    int gy = gy0 + r, gx = gx0 + col;
    float v = 0.f;
    if (gy >= 0 && gy < HH && gx >= 0 && gx < WW)
      v = sigm_pre(fmaf(sa[c], __half2float(H[(size_t)(n*16+sch[c])*HWp + gy*WW + gx]), sbb[c]));
    sp[c][r][col] = v;
  }
  __syncthreads();

  int tx = t & 15, ty = t >> 4;
  int by = 2*ty, bx = 2*tx;
  u64t aA[8], aB[8];
#pragma unroll
  for (int oc=0;oc<8;oc++){ aA[oc]=DBC1(oc); aB[oc]=DBC1(oc); }
#pragma unroll
  for (int c=0;c<3;c++)
#pragma unroll
    for (int ky=0;ky<3;ky++)
#pragma unroll
      for (int kx=0;kx<3;kx++){
        u64t vA = pk2(sp[c][by+ky  ][bx+kx], sp[c][by+ky  ][bx+kx+1]);
        u64t vB = pk2(sp[c][by+ky+1][bx+kx], sp[c][by+ky+1][bx+kx+1]);
#pragma unroll
        for (int oc=0;oc<8;oc++){
          u64t wv = DWC1(oc*27 + c*9 + ky*3 + kx);
          aA[oc] = fma2(wv, vA, aA[oc]);
          aB[oc] = fma2(wv, vB, aB[oc]);
        }
      }
  int py = blockIdx.y*16 + ty, px = blockIdx.x*16 + tx;
#pragma unroll
  for (int oc=0;oc<8;oc++){
    float a00,a01,a10,a11;
    upk2(aA[oc],a00,a01); upk2(aB[oc],a10,a11);
    float mx = fmaxf(fmaxf(a00,a01), fmaxf(a10,a11));
    g_x1[(size_t)(n*8+oc)*65536 + py*256 + px] = sigm(mx);  // sigmoid monotone
  }
}

// ---------------- K_conv3b: conv3x3(8->16)+sigm+pool ----------------
__global__ void __launch_bounds__(256,2) k_conv3b(){
  __shared__ float sp[8][34][36];
  int n = blockIdx.z;
  int t = threadIdx.x;

  int gy0 = blockIdx.y*32 - 1, gx0 = blockIdx.x*32 - 1;
  for (int i=t; i < 8*34*34; i += 256){
    int c = i / 1156, rem = i % 1156;
    int r = rem / 34, col = rem % 34;
    int gy = gy0 + r, gx = gx0 + col;
    float v = 0.f;
    if (gy >= 0 && gy < 256 && gx >= 0 && gx < 256)
      v = g_x1[(size_t)(n*8+c)*65536 + gy*256 + gx];
    sp[c][r][col] = v;
  }
  __syncthreads();

  int tx = t & 15, ty = t >> 4;
  int by = 2*ty, bx = 2*tx;
  u64t aA[16], aB[16];
#pragma unroll
  for (int oc=0;oc<16;oc++){ aA[oc]=DBC2(oc); aB[oc]=DBC2(oc); }
#pragma unroll
  for (int c=0;c<8;c++)
#pragma unroll
    for (int ky=0;ky<3;ky++)
#pragma unroll
      for (int kx=0;kx<3;kx++){
        u64t vA = pk2(sp[c][by+ky  ][bx+kx], sp[c][by+ky  ][bx+kx+1]);
        u64t vB = pk2(sp[c][by+ky+1][bx+kx], sp[c][by+ky+1][bx+kx+1]);
#pragma unroll
        for (int oc=0;oc<16;oc++){
          u64t wv = DWC2(oc*72 + c*9 + ky*3 + kx);
          aA[oc] = fma2(wv, vA, aA[oc]);
          aB[oc] = fma2(wv, vB, aB[oc]);
        }
      }
  int py = blockIdx.y*16 + ty, px = blockIdx.x*16 + tx;
#pragma unroll
  for (int oc=0;oc<16;oc++){
    float a00,a01,a10,a11;
    upk2(aA[oc],a00,a01); upk2(aB[oc],a10,a11);
    float mx = fmaxf(fmaxf(a00,a01), fmaxf(a10,a11));
    g_x2[(size_t)(n*16+oc)*16384 + py*128 + px] = sigm(mx);
  }
}

// ---- vertical index helpers (jax half-pixel bilinear, clamped) ----
__device__ __forceinline__ void idx_up2(int h, int Hin, int& y0, int& y1, float& f){
  y0 = (h >> 1) - ((h & 1) ^ 1);
  f  = (h & 1) ? 0.25f : 0.75f;
  y1 = min(y0 + 1, Hin - 1);
  y0 = max(y0, 0);
}
__device__ __forceinline__ void idx_up4(int h, int Hin, int& y0, int& y1, float& f){
  int m = h & 3;
  y0 = (h >> 2) - (m < 2 ? 1 : 0);
  f  = (m==0) ? 0.625f : (m==1) ? 0.875f : (m==2) ? 0.125f : 0.375f;
  y1 = min(y0 + 1, Hin - 1);
  y0 = max(y0, 0);
}
#define LERP(a,b,f) ((a) + (f)*((b)-(a)))

// sigmoid outputs > 0 and bilinear weights nonneg => relu identity on up paths.

// ---------------- K_upstats: stats of up2(x1) and up4(x2), merged ----------------
__global__ void __launch_bounds__(256,2) k_upstats(){
  __shared__ double ssum[24], ssq[24];
  int t = threadIdx.x;
  if (t < 24){ ssum[t]=0.0; ssq[t]=0.0; }
  __syncthreads();

  float s[24], q[24];
#pragma unroll
  for (int c=0;c<24;c++){ s[c]=0.f; q[c]=0.f; }

  const int NQ = NHWp/4;
  int stride = gridDim.x * blockDim.x;
  for (int p = blockIdx.x*blockDim.x + t; p < NQ; p += stride){
    int n = p >> 16, r = p & 65535;
    int h = r >> 7, w = r & 127;
    {   // up2 path
      int y0,y1; float fy; idx_up2(h,256,y0,y1,fy);
      int c0 = max(2*w-1,0), c1 = 2*w, c2 = 2*w+1, c3 = min(2*w+2,255);
      const float* bp = g_x1 + (size_t)n*8*65536;
#pragma unroll
      for (int c=0;c<8;c++){
        const float* p0 = bp + (size_t)c*65536 + y0*256;
        const float* p1 = bp + (size_t)c*65536 + y1*256;
        float vv0 = LERP(p0[c0], p1[c0], fy);
        float vv1 = LERP(p0[c1], p1[c1], fy);
        float vv2 = LERP(p0[c2], p1[c2], fy);
        float vv3 = LERP(p0[c3], p1[c3], fy);
        float o0 = LERP(vv0, vv1, 0.75f);
        float o1 = LERP(vv1, vv2, 0.25f);
        float o2 = LERP(vv1, vv2, 0.75f);
        float o3 = LERP(vv2, vv3, 0.25f);
        s[c] += (o0+o1) + (o2+o3);
        q[c] = fmaf(o0,o0, fmaf(o1,o1, fmaf(o2,o2, fmaf(o3,o3, q[c]))));
      }
    }
    {   // up4 path
      int y0,y1; float fy; idx_up4(h,128,y0,y1,fy);
      int cm = max(w-1,0), cc = w, cp = min(w+1,127);
      const float* bp = g_x2 + (size_t)n*16*16384;
#pragma unroll
      for (int c=0;c<16;c++){
        const float* p0 = bp + (size_t)c*16384 + y0*128;
        const float* p1 = bp + (size_t)c*16384 + y1*128;
        float vv0 = LERP(p0[cm], p1[cm], fy);
        float vv1 = LERP(p0[cc], p1[cc], fy);
        float vv2 = LERP(p0[cp], p1[cp], fy);
        float o0 = LERP(vv0, vv1, 0.625f);
        float o1 = LERP(vv0, vv1, 0.875f);
        float o2 = LERP(vv1, vv2, 0.125f);
        float o3 = LERP(vv1, vv2, 0.375f);
        s[8+c] += (o0+o1) + (o2+o3);
        q[8+c] = fmaf(o0,o0, fmaf(o1,o1, fmaf(o2,o2, fmaf(o3,o3, q[8+c]))));
      }
    }
  }
#pragma unroll
  for (int c=0;c<24;c++){
    float a=s[c], b=q[c];
#pragma unroll
    for (int o=16;o>0;o>>=1){ a += __shfl_down_sync(0xffffffffu,a,o); b += __shfl_down_sync(0xffffffffu,b,o); }
    if ((t&31)==0){ atomicAdd(&ssum[c],(double)a); atomicAdd(&ssq[c],(double)b); }
  }
  __syncthreads();
  if (t<24){ atomicAdd(&g_usum[t], ssum[t]); atomicAdd(&g_usq[t], ssq[t]); }
}

// ---------------- K_final: (up BN coeffs) + up2/up4 + BN + concat + 1x1 conv ----------------
__global__ void __launch_bounds__(256,3) k_final(float* __restrict__ out,
                                                 const float* __restrict__ gbn1,
                                                 const float* __restrict__ bbn1,
                                                 const float* __restrict__ gbn2,
                                                 const float* __restrict__ bbn2){
  __shared__ float sa[24], sbb[24];
  int t = threadIdx.x;
  if (t < 24){
    double m = g_usum[t] / (double)NHWp;
    double v = g_usq[t]  / (double)NHWp - m*m;
    double gamma = (t < 8) ? (double)gbn2[t] : (double)gbn1[t-8];
    double beta  = (t < 8) ? (double)bbn2[t] : (double)bbn1[t-8];
    double a = gamma / sqrt(v + 1e-5);
    sa[t]  = (float)a;
    sbb[t] = (float)(beta - a*m);
  }
  __syncthreads();

  const int NQ = NHWp/4;
  int stride = gridDim.x * blockDim.x;
  for (int p = blockIdx.x*blockDim.x + t; p < NQ; p += stride){
    int n = p >> 16, r = p & 65535;
    int h = r >> 7, w = r & 127;

    u64t a01[5], a23[5];
#pragma unroll
    for (int k=0;k<5;k++){ a01[k]=DB1K(k); a23[k]=DB1K(k); }

    {   // up2 path: channels 0..7
      int y0,y1; float fy; idx_up2(h,256,y0,y1,fy);
      int c0 = max(2*w-1,0), c1 = 2*w, c2 = 2*w+1, c3 = min(2*w+2,255);
      const float* bp = g_x1 + (size_t)n*8*65536;
#pragma unroll
      for (int c=0;c<8;c++){
        const float* p0 = bp + (size_t)c*65536 + y0*256;
        const float* p1 = bp + (size_t)c*65536 + y1*256;
        float vv0 = LERP(p0[c0], p1[c0], fy);
        float vv1 = LERP(p0[c1], p1[c1], fy);
        float vv2 = LERP(p0[c2], p1[c2], fy);
        float vv3 = LERP(p0[c3], p1[c3], fy);
        float sc = sa[c], sh = sbb[c];
        float r0 = fmaf(sc, LERP(vv0, vv1, 0.75f), sh);
        float r1 = fmaf(sc, LERP(vv1, vv2, 0.25f), sh);
        float r2 = fmaf(sc, LERP(vv1, vv2, 0.75f), sh);
        float r3 = fmaf(sc, LERP(vv2, vv3, 0.25f), sh);
        u64t r01 = pk2(r0,r1), r23 = pk2(r2,r3);
#pragma unroll
        for (int k=0;k<5;k++){
          u64t wv = DW1K(k*24+c);
          a01[k] = fma2(wv, r01, a01[k]);
          a23[k] = fma2(wv, r23, a23[k]);
        }
      }
    }
    {   // up4 path: channels 8..23
      int y0,y1; float fy; idx_up4(h,128,y0,y1,fy);
      int cm = max(w-1,0), cc = w, cp = min(w+1,127);
      const float* bp = g_x2 + (size_t)n*16*16384;
#pragma unroll
      for (int c=0;c<16;c++){
        const float* p0 = bp + (size_t)c*16384 + y0*128;
        const float* p1 = bp + (size_t)c*16384 + y1*128;
        float vv0 = LERP(p0[cm], p1[cm], fy);
        float vv1 = LERP(p0[cc], p1[cc], fy);
        float vv2 = LERP(p0[cp], p1[cp], fy);
        float sc = sa[8+c], sh = sbb[8+c];
        float r0 = fmaf(sc, LERP(vv0, vv1, 0.625f), sh);
        float r1 = fmaf(sc, LERP(vv0, vv1, 0.875f), sh);
        float r2 = fmaf(sc, LERP(vv1, vv2, 0.125f), sh);
        float r3 = fmaf(sc, LERP(vv1, vv2, 0.375f), sh);
        u64t r01 = pk2(r0,r1), r23 = pk2(r2,r3);
#pragma unroll
        for (int k=0;k<5;k++){
          u64t wv = DW1K(k*24+8+c);
          a01[k] = fma2(wv, r01, a01[k]);
          a23[k] = fma2(wv, r23, a23[k]);
        }
      }
    }
#pragma unroll
    for (int k=0;k<5;k++){
      float4 v;
      upk2(a01[k], v.x, v.y);
      upk2(a23[k], v.z, v.w);
      *(float4*)(out + (size_t)(n*5+k)*HWp + h*512 + 4*w) = v;
    }
  }
}

// ---------------- launch ----------------
extern "C" void kernel_launch(void* const* d_in, const int* in_sizes, int n_in,
                              void* d_out, int out_size){
  (void)in_sizes; (void)n_in; (void)out_size;
  const float* x       = (const float*)d_in[0];
  const float* g_ebn1  = (const float*)d_in[3];
  const float* be_ebn1 = (const float*)d_in[4];
  const float* g_ebn2  = (const float*)d_in[7];
  const float* be_ebn2 = (const float*)d_in[8];
  const float* g_bn1   = (const float*)d_in[13];
  const float* be_bn1  = (const float*)d_in[14];
  const float* g_bn2   = (const float*)d_in[15];
  const float* be_bn2  = (const float*)d_in[16];
  float* out = (float*)d_out;

  cudaMemcpyToSymbolAsync(c_w1, d_in[1], 160*sizeof(float), 0, cudaMemcpyDeviceToDevice, 0);
  cudaMemcpyToSymbolAsync(c_b1, d_in[2],  16*sizeof(float), 0, cudaMemcpyDeviceToDevice, 0);

  k_init<<<8,256>>>((const float*)d_in[1],  (const float*)d_in[2],
                    (const float*)d_in[5],  (const float*)d_in[6],
                    (const float*)d_in[9],  (const float*)d_in[10],
                    (const float*)d_in[11], (const float*)d_in[12],
                    (const float*)d_in[17], (const float*)d_in[18]);
  void* pdup = nullptr;
  cudaGetSymbolAddress(&pdup, g_dup);
  cudaMemcpyToSymbolAsync(c_dup, pdup, NDUP*sizeof(u64t), 0, cudaMemcpyDeviceToDevice, 0);

  const int GS2 = 1184;   // occ-2 kernels: 148*8
  const int GS3 = 1332;   // occ-3 kernels: 148*9

  k_cov<<<GS2,256>>>(x);
  k_fused<<<GS2,256>>>(x, g_ebn1, be_ebn1);
  k_varstats<<<2048,256>>>(g_ebn2, be_ebn2);
  k_conv3a<<<dim3(16,16,16),256>>>(g_ebn2, be_ebn2);
  k_conv3b<<<dim3(8,8,16),256>>>();
  k_upstats<<<GS2,256>>>();
  k_final<<<GS3,256>>>(out, g_bn1, be_bn1, g_bn2, be_bn2);
}